// round 9
// baseline (speedup 1.0000x reference)
#include <cuda_runtime.h>
#include <cstdint>

// SpikeFP32Adder — integer re-implementation of the soft-gate FP32 adder.
// R9: R4 structure + register-budget unlock. __launch_bounds__(256,4) lifts
// the reg ceiling to 64 so the 8-row load batches can ACTUALLY be hoisted
// (R6 batched under a 36-reg cap -> ptxas couldn't, and scheduled worse).
// 32 warps/SM x ~16 in-flight loads each > 47 warps x ~6: more MLP total.

__device__ __forceinline__ unsigned spike_fp32_add(unsigned ra, unsigned rb) {
    const unsigned sa = ra >> 31, sb = rb >> 31;
    const unsigned ea = (ra >> 23) & 0xFFu, eb = (rb >> 23) & 0xFFu;

    const unsigned eae = ea ? ea : 1u;                      // e_eff
    const unsigned ebe = eb ? eb : 1u;
    const unsigned manta = (ra & 0x7FFFFFu) | ((ea ? 1u : 0u) << 23);
    const unsigned mantb = (rb & 0x7FFFFFu) | ((eb ? 1u : 0u) << 23);

    const bool exp_eq = (eae == ebe);
    const bool a_ge_b = (eae > ebe) || (exp_eq && (manta >= mantb));
    const bool abs_eq = exp_eq && (manta == mantb);

    const unsigned ediff = a_ge_b ? (eae - ebe) : (ebe - eae);
    const bool big = (ediff >= 24u);                        // is_big_diff
    const unsigned shift = big ? 0u : ediff;

    const unsigned emax = a_ge_b ? eae : ebe;
    const unsigned Ml  = (a_ge_b ? manta : mantb) << 4;     // 28-bit
    const unsigned Ms0 = (a_ge_b ? mantb : manta) << 4;

    const bool sticky = (Ms0 & ((1u << shift) - 1u)) != 0u;
    const unsigned Ms = Ms0 >> shift;

    const unsigned ds = sa ^ sb;                            // diff sign
    const bool exact_cancel = (ds != 0u) && abs_eq;
    const unsigned s_large = a_ge_b ? sa : sb;

    const unsigned sum = Ml + Ms;
    const unsigned diff = (Ml - Ms - ((ds && sticky) ? 1u : 0u)) & 0xFFFFFFFu;
    const unsigned res_carry = ds ? 0u : ((sum >> 28) & 1u);
    const unsigned mant_res = ds ? diff : (sum & 0xFFFFFFFu);

    const unsigned lzc = (unsigned)__clz(mant_res) - 4u;    // 0..28
    const bool underflow = (lzc >= emax);
    const unsigned norm_m = (mant_res << lzc) & 0xFFFFFFFu;

    const unsigned e_after  = (emax - lzc) & 0xFFu;
    const unsigned e_plus1  = (emax + 1u) & 0xFFu;
    const unsigned e_normal = underflow ? 0u : e_after;
    const unsigned final_e  = res_carry ? e_plus1 : e_normal;

    const unsigned m_pre = res_carry ? ((mant_res >> 5) & 0x7FFFFFu)
                                     : ((norm_m  >> 4) & 0x7FFFFFu);
    const unsigned r_pre = res_carry ? ((mant_res >> 4) & 1u)
                                     : ((norm_m  >> 3) & 1u);
    const bool st_raw = res_carry ? ((mant_res & 0xFu) != 0u)
                                  : ((norm_m  & 0x7u) != 0u);
    const bool st_pre = st_raw || ((ds == 0u) && sticky);

    const unsigned m_sel = underflow ? ((mant_res >> 5) & 0x7FFFFFu) : m_pre;
    const unsigned L = m_sel & 1u;
    const unsigned do_round =
        ((r_pre != 0u) && (st_pre || (L != 0u)) && !underflow) ? 1u : 0u;

    // Circuit quirk: round-adder carry-out is structurally 0 — mantissa wraps
    // to 0 on rounding overflow WITHOUT exponent increment.
    const unsigned m_final = (m_sel + do_round) & 0x7FFFFFu;

    const bool inf = (final_e == 0xFFu);
    unsigned cs = exact_cancel ? 0u : s_large;
    unsigned ce = exact_cancel ? 0u : final_e;
    unsigned cm = exact_cancel ? 0u : m_final;
    cs = inf ? s_large : cs;
    ce = inf ? 0xFFu   : ce;
    cm = inf ? 0u      : cm;

    const unsigned normal = (cs << 31) | (ce << 23) | cm;
    const unsigned larger = a_ge_b ? ra : rb;
    return big ? larger : normal;
}

// 32x32 bit-matrix transpose across a warp.
__device__ __forceinline__ unsigned bit_transpose32(unsigned t, unsigned lane) {
    unsigned y;
    y = __shfl_xor_sync(0xFFFFFFFFu, t, 16);
    t = (lane & 16) ? ((t & 0xFFFF0000u) | (y >> 16))
                    : ((t & 0x0000FFFFu) | (y << 16));
    y = __shfl_xor_sync(0xFFFFFFFFu, t, 8);
    t = (lane & 8) ? ((t & 0xFF00FF00u) | ((y >> 8) & 0x00FF00FFu))
                   : ((t & 0x00FF00FFu) | ((y << 8) & 0xFF00FF00u));
    y = __shfl_xor_sync(0xFFFFFFFFu, t, 4);
    t = (lane & 4) ? ((t & 0xF0F0F0F0u) | ((y >> 4) & 0x0F0F0F0Fu))
                   : ((t & 0x0F0F0F0Fu) | ((y << 4) & 0xF0F0F0F0u));
    y = __shfl_xor_sync(0xFFFFFFFFu, t, 2);
    t = (lane & 2) ? ((t & 0xCCCCCCCCu) | ((y >> 2) & 0x33333333u))
                   : ((t & 0x33333333u) | ((y << 2) & 0xCCCCCCCCu));
    y = __shfl_xor_sync(0xFFFFFFFFu, t, 1);
    t = (lane & 1) ? ((t & 0xAAAAAAAAu) | ((y >> 1) & 0x55555555u))
                   : ((t & 0x55555555u) | ((y << 1) & 0xAAAAAAAAu));
    return t;
}

// Deposit bit 23 of word u (0x3F800000 or 0) into bit i.
__device__ __forceinline__ unsigned depb(unsigned u, int i) {
    return (i <= 23) ? ((u >> (23 - i)) & (1u << i))
                     : ((u << (i - 23)) & (1u << i));
}

__device__ __forceinline__ void process_tile(const unsigned* __restrict__ A,
                                             const unsigned* __restrict__ B,
                                             float* __restrict__ O,
                                             int tile, unsigned lane) {
    const size_t elemBase = (size_t)tile * 32 * 32;     // 32 rows * 32 cols
    const unsigned* pa = A + elemBase + (31 - lane);    // lane l -> column 31-l
    const unsigned* pb = B + elemBase + (31 - lane);

    // Pack: bit 23 (set iff value==1.0f) of row i goes to bit i.
    // 4 chunks of 8 rows; all 16 loads of a chunk materialized before use
    // (needs the 64-reg budget from __launch_bounds__(256,4) to hoist).
    unsigned ca = 0u, cb = 0u;
    #pragma unroll
    for (int c = 0; c < 4; c++) {
        unsigned ta[8], tb[8];
        #pragma unroll
        for (int j = 0; j < 8; j++) ta[j] = __ldcs(pa + (c * 8 + j) * 32);
        #pragma unroll
        for (int j = 0; j < 8; j++) tb[j] = __ldcs(pb + (c * 8 + j) * 32);
        #pragma unroll
        for (int j = 0; j < 8; j++) {
            ca |= depb(ta[j], c * 8 + j);
            cb |= depb(tb[j], c * 8 + j);
        }
    }

    // Transpose -> lane r holds row r's word in IEEE layout.
    const unsigned ra = bit_transpose32(ca, lane);
    const unsigned rb = bit_transpose32(cb, lane);

    const unsigned res = spike_fp32_add(ra, rb);        // per-lane row

    // Unpack: iteration i stores rows 4i..4i+3 (512B) with STG.128.
    float* po = O + elemBase;
    #pragma unroll
    for (int i = 0; i < 8; i++) {
        const int src = i * 4 + (lane >> 3);
        const unsigned w = __shfl_sync(0xFFFFFFFFu, res, src);
        const unsigned w2 = w << ((lane & 7) * 4);
        float4 f;
        f.x = __uint_as_float(((unsigned)((int)(w2     ) >> 31)) & 0x3F800000u);
        f.y = __uint_as_float(((unsigned)((int)(w2 << 1) >> 31)) & 0x3F800000u);
        f.z = __uint_as_float(((unsigned)((int)(w2 << 2) >> 31)) & 0x3F800000u);
        f.w = __uint_as_float(((unsigned)((int)(w2 << 3) >> 31)) & 0x3F800000u);
        *reinterpret_cast<float4*>(po + i * 128 + (lane >> 3) * 32 + (lane & 7) * 4) = f;
    }
}

__global__ void __launch_bounds__(256, 4)
spike_adder_kernel(const unsigned* __restrict__ A,
                   const unsigned* __restrict__ B,
                   float* __restrict__ O,
                   int nwarpTiles, int totalWarps) {
    const int warpId = blockIdx.x * (blockDim.x >> 5) + (threadIdx.x >> 5);
    const unsigned lane = threadIdx.x & 31;

    for (int t = warpId; t < nwarpTiles; t += totalWarps)
        process_tile(A, B, O, t, lane);
}

// Scalar tail kernel (warp-per-row) for nrows % 32 != 0.
__global__ void spike_adder_tail(const float* __restrict__ A,
                                 const float* __restrict__ B,
                                 float* __restrict__ O,
                                 int rowStart, int nrows) {
    const int row = rowStart + blockIdx.x;
    const int lane = threadIdx.x & 31;
    if (row >= nrows) return;
    const size_t base = (size_t)row * 32 + lane;
    const unsigned ua = __ballot_sync(0xFFFFFFFFu, A[base] != 0.0f);
    const unsigned ub = __ballot_sync(0xFFFFFFFFu, B[base] != 0.0f);
    const unsigned res = spike_fp32_add(__brev(ua), __brev(ub));
    const unsigned f = ((unsigned)((int)(res << lane) >> 31)) & 0x3F800000u;
    O[base] = __uint_as_float(f);
}

extern "C" void kernel_launch(void* const* d_in, const int* in_sizes, int n_in,
                              void* d_out, int out_size) {
    const float* A = (const float*)d_in[0];
    const float* B = (const float*)d_in[1];
    float* O = (float*)d_out;

    const int nrows = in_sizes[0] / 32;
    const int nwarpTiles = nrows / 32;
    const int tailRows = nrows - nwarpTiles * 32;

    if (nwarpTiles > 0) {
        const int threads = 256;
        const int warpsPerBlock = threads / 32;         // 8
        // 4 blocks/SM resident now -> capacity 592 blocks. Use 4 tiles/warp:
        // 16384 tiles / (8*4) = 512 blocks <= 592 -> single balanced wave.
        const int tilesPerWarp = 4;
        int blocks = (nwarpTiles + warpsPerBlock * tilesPerWarp - 1) /
                     (warpsPerBlock * tilesPerWarp);    // 512 for N=524288
        const int totalWarps = blocks * warpsPerBlock;
        spike_adder_kernel<<<blocks, threads>>>(
            (const unsigned*)A, (const unsigned*)B, O, nwarpTiles, totalWarps);
    }
    if (tailRows > 0) {
        spike_adder_tail<<<tailRows, 32>>>(A, B, O, nwarpTiles * 32, nrows);
    }
}

// round 10
// speedup vs baseline: 1.1058x; 1.1058x over previous
#include <cuda_runtime.h>
#include <cstdint>

// SpikeFP32Adder — integer re-implementation of the soft-gate FP32 adder.
// FINAL (= R4/R8 config, reproduced twice at 33.2/33.3us wall, 28.9/29.8us
// kernel). The kernel sits at the chip's mixed read/write memory envelope:
// 192 MiB irreducible traffic at ~6.9 TB/s apparent. Searched to regression
// on both sides:
//   - instruction restructuring (LDG.128 R5, batched LDG.32 R6): slower
//   - cache policy (__ldg/__stcs R7): slower wall
//   - occupancy/MLP trade (regs 63, occ 39% R9): slower
// Winning recipe: warp-per-32-row-tile, 1-bit pack via shift+LOP3, 5-stage
// shfl_xor 32x32 bit transpose, per-lane integer adder circuit (bit-exact
// vs the soft-gate reference incl. its non-IEEE quirks), STG.128 unpack,
// __ldcs loads + plain stores, 1024 blocks = single balanced wave.

__device__ __forceinline__ unsigned spike_fp32_add(unsigned ra, unsigned rb) {
    const unsigned sa = ra >> 31, sb = rb >> 31;
    const unsigned ea = (ra >> 23) & 0xFFu, eb = (rb >> 23) & 0xFFu;

    const unsigned eae = ea ? ea : 1u;                      // e_eff
    const unsigned ebe = eb ? eb : 1u;
    const unsigned manta = (ra & 0x7FFFFFu) | ((ea ? 1u : 0u) << 23);
    const unsigned mantb = (rb & 0x7FFFFFu) | ((eb ? 1u : 0u) << 23);

    const bool exp_eq = (eae == ebe);
    const bool a_ge_b = (eae > ebe) || (exp_eq && (manta >= mantb));
    const bool abs_eq = exp_eq && (manta == mantb);

    const unsigned ediff = a_ge_b ? (eae - ebe) : (ebe - eae);
    const bool big = (ediff >= 24u);                        // is_big_diff
    const unsigned shift = big ? 0u : ediff;

    const unsigned emax = a_ge_b ? eae : ebe;
    const unsigned Ml  = (a_ge_b ? manta : mantb) << 4;     // 28-bit
    const unsigned Ms0 = (a_ge_b ? mantb : manta) << 4;

    const bool sticky = (Ms0 & ((1u << shift) - 1u)) != 0u;
    const unsigned Ms = Ms0 >> shift;

    const unsigned ds = sa ^ sb;                            // diff sign
    const bool exact_cancel = (ds != 0u) && abs_eq;
    const unsigned s_large = a_ge_b ? sa : sb;

    const unsigned sum = Ml + Ms;
    const unsigned diff = (Ml - Ms - ((ds && sticky) ? 1u : 0u)) & 0xFFFFFFFu;
    const unsigned res_carry = ds ? 0u : ((sum >> 28) & 1u);
    const unsigned mant_res = ds ? diff : (sum & 0xFFFFFFFu);

    const unsigned lzc = (unsigned)__clz(mant_res) - 4u;    // 0..28
    const bool underflow = (lzc >= emax);
    const unsigned norm_m = (mant_res << lzc) & 0xFFFFFFFu;

    const unsigned e_after  = (emax - lzc) & 0xFFu;
    const unsigned e_plus1  = (emax + 1u) & 0xFFu;
    const unsigned e_normal = underflow ? 0u : e_after;
    const unsigned final_e  = res_carry ? e_plus1 : e_normal;

    const unsigned m_pre = res_carry ? ((mant_res >> 5) & 0x7FFFFFu)
                                     : ((norm_m  >> 4) & 0x7FFFFFu);
    const unsigned r_pre = res_carry ? ((mant_res >> 4) & 1u)
                                     : ((norm_m  >> 3) & 1u);
    const bool st_raw = res_carry ? ((mant_res & 0xFu) != 0u)
                                  : ((norm_m  & 0x7u) != 0u);
    const bool st_pre = st_raw || ((ds == 0u) && sticky);

    const unsigned m_sel = underflow ? ((mant_res >> 5) & 0x7FFFFFu) : m_pre;
    const unsigned L = m_sel & 1u;
    const unsigned do_round =
        ((r_pre != 0u) && (st_pre || (L != 0u)) && !underflow) ? 1u : 0u;

    // Circuit quirk: round-adder carry-out is structurally 0 — mantissa wraps
    // to 0 on rounding overflow WITHOUT exponent increment.
    const unsigned m_final = (m_sel + do_round) & 0x7FFFFFu;

    const bool inf = (final_e == 0xFFu);
    unsigned cs = exact_cancel ? 0u : s_large;
    unsigned ce = exact_cancel ? 0u : final_e;
    unsigned cm = exact_cancel ? 0u : m_final;
    cs = inf ? s_large : cs;
    ce = inf ? 0xFFu   : ce;
    cm = inf ? 0u      : cm;

    const unsigned normal = (cs << 31) | (ce << 23) | cm;
    const unsigned larger = a_ge_b ? ra : rb;
    return big ? larger : normal;
}

// 32x32 bit-matrix transpose across a warp.
__device__ __forceinline__ unsigned bit_transpose32(unsigned t, unsigned lane) {
    unsigned y;
    y = __shfl_xor_sync(0xFFFFFFFFu, t, 16);
    t = (lane & 16) ? ((t & 0xFFFF0000u) | (y >> 16))
                    : ((t & 0x0000FFFFu) | (y << 16));
    y = __shfl_xor_sync(0xFFFFFFFFu, t, 8);
    t = (lane & 8) ? ((t & 0xFF00FF00u) | ((y >> 8) & 0x00FF00FFu))
                   : ((t & 0x00FF00FFu) | ((y << 8) & 0xFF00FF00u));
    y = __shfl_xor_sync(0xFFFFFFFFu, t, 4);
    t = (lane & 4) ? ((t & 0xF0F0F0F0u) | ((y >> 4) & 0x0F0F0F0Fu))
                   : ((t & 0x0F0F0F0Fu) | ((y << 4) & 0xF0F0F0F0u));
    y = __shfl_xor_sync(0xFFFFFFFFu, t, 2);
    t = (lane & 2) ? ((t & 0xCCCCCCCCu) | ((y >> 2) & 0x33333333u))
                   : ((t & 0x33333333u) | ((y << 2) & 0xCCCCCCCCu));
    y = __shfl_xor_sync(0xFFFFFFFFu, t, 1);
    t = (lane & 1) ? ((t & 0xAAAAAAAAu) | ((y >> 1) & 0x55555555u))
                   : ((t & 0x55555555u) | ((y << 1) & 0xAAAAAAAAu));
    return t;
}

__device__ __forceinline__ void process_tile(const unsigned* __restrict__ A,
                                             const unsigned* __restrict__ B,
                                             float* __restrict__ O,
                                             int tile, unsigned lane) {
    const size_t elemBase = (size_t)tile * 32 * 32;     // 32 rows * 32 cols
    const unsigned* pa = A + elemBase + (31 - lane);    // lane l -> column 31-l
    const unsigned* pb = B + elemBase + (31 - lane);

    // Pack: bit 23 (set iff value==1.0f) of row i goes to bit i.
    unsigned ca = 0u, cb = 0u;
    #pragma unroll
    for (int i = 0; i < 32; i++) {
        const unsigned ua = __ldcs(pa + i * 32);
        const unsigned ub = __ldcs(pb + i * 32);
        if (i <= 23) {
            ca |= (ua >> (23 - i)) & (1u << i);
            cb |= (ub >> (23 - i)) & (1u << i);
        } else {
            ca |= (ua << (i - 23)) & (1u << i);
            cb |= (ub << (i - 23)) & (1u << i);
        }
    }

    // Transpose -> lane r holds row r's word in IEEE layout.
    const unsigned ra = bit_transpose32(ca, lane);
    const unsigned rb = bit_transpose32(cb, lane);

    const unsigned res = spike_fp32_add(ra, rb);        // per-lane row

    // Unpack: iteration i stores rows 4i..4i+3 (512B) with STG.128.
    float* po = O + elemBase;
    #pragma unroll
    for (int i = 0; i < 8; i++) {
        const int src = i * 4 + (lane >> 3);
        const unsigned w = __shfl_sync(0xFFFFFFFFu, res, src);
        const unsigned w2 = w << ((lane & 7) * 4);
        float4 f;
        f.x = __uint_as_float(((unsigned)((int)(w2     ) >> 31)) & 0x3F800000u);
        f.y = __uint_as_float(((unsigned)((int)(w2 << 1) >> 31)) & 0x3F800000u);
        f.z = __uint_as_float(((unsigned)((int)(w2 << 2) >> 31)) & 0x3F800000u);
        f.w = __uint_as_float(((unsigned)((int)(w2 << 3) >> 31)) & 0x3F800000u);
        *reinterpret_cast<float4*>(po + i * 128 + (lane >> 3) * 32 + (lane & 7) * 4) = f;
    }
}

__global__ void __launch_bounds__(256)
spike_adder_kernel(const unsigned* __restrict__ A,
                   const unsigned* __restrict__ B,
                   float* __restrict__ O,
                   int nwarpTiles, int totalWarps) {
    const int warpId = blockIdx.x * (blockDim.x >> 5) + (threadIdx.x >> 5);
    const unsigned lane = threadIdx.x & 31;

    // Strided grid-stride over tiles: with grid sized for 2 tiles/warp this
    // executes exactly twice for (almost) every warp -> single balanced wave.
    for (int t = warpId; t < nwarpTiles; t += totalWarps)
        process_tile(A, B, O, t, lane);
}

// Scalar tail kernel (warp-per-row) for nrows % 32 != 0.
__global__ void spike_adder_tail(const float* __restrict__ A,
                                 const float* __restrict__ B,
                                 float* __restrict__ O,
                                 int rowStart, int nrows) {
    const int row = rowStart + blockIdx.x;
    const int lane = threadIdx.x & 31;
    if (row >= nrows) return;
    const size_t base = (size_t)row * 32 + lane;
    const unsigned ua = __ballot_sync(0xFFFFFFFFu, A[base] != 0.0f);
    const unsigned ub = __ballot_sync(0xFFFFFFFFu, B[base] != 0.0f);
    const unsigned res = spike_fp32_add(__brev(ua), __brev(ub));
    const unsigned f = ((unsigned)((int)(res << lane) >> 31)) & 0x3F800000u;
    O[base] = __uint_as_float(f);
}

extern "C" void kernel_launch(void* const* d_in, const int* in_sizes, int n_in,
                              void* d_out, int out_size) {
    const float* A = (const float*)d_in[0];
    const float* B = (const float*)d_in[1];
    float* O = (float*)d_out;

    const int nrows = in_sizes[0] / 32;
    const int nwarpTiles = nrows / 32;
    const int tailRows = nrows - nwarpTiles * 32;

    if (nwarpTiles > 0) {
        const int threads = 256;
        const int warpsPerBlock = threads / 32;         // 8
        const int tilesPerWarp = 2;
        int blocks = (nwarpTiles + warpsPerBlock * tilesPerWarp - 1) /
                     (warpsPerBlock * tilesPerWarp);    // 1024 for N=524288
        const int totalWarps = blocks * warpsPerBlock;
        spike_adder_kernel<<<blocks, threads>>>(
            (const unsigned*)A, (const unsigned*)B, O, nwarpTiles, totalWarps);
    }
    if (tailRows > 0) {
        spike_adder_tail<<<tailRows, 32>>>(A, B, O, nwarpTiles * 32, nrows);
    }
}